// round 7
// baseline (speedup 1.0000x reference)
#include <cuda_runtime.h>
#include <cuda_bf16.h>
#include <cstdint>

#define B_ 32
#define L_ 2048
#define D_ 768
#define H_ 512
#define M_ (B_*L_)   // 65536 tokens

// ---- scratch (__device__ globals per allocation rules) ----
__device__ float g_h[(size_t)M_ * H_];          // 134 MB intermediate h
__device__ __nv_bfloat16 g_a_hi[(size_t)M_ * D_];   // hidden bf16 hi (100MB)
__device__ __nv_bfloat16 g_a_lo[(size_t)M_ * D_];   // hidden bf16 lo
__device__ __nv_bfloat16 g_w1t_hi[H_ * D_];     // W1 transposed, bf16 hi
__device__ __nv_bfloat16 g_w1t_lo[H_ * D_];     // W1 transposed, bf16 lo
__device__ float g_sum[H_];
__device__ float g_sumsq[H_];
__device__ float g_scale[H_];
__device__ float g_shift[H_];
__device__ float g_counts[B_];
__device__ float g_pooled[B_ * H_];

// =====================================================================
// helpers
// =====================================================================
__device__ __forceinline__ void mma16816(float* c, const uint32_t* a,
                                         const uint32_t* b) {
    asm volatile(
        "mma.sync.aligned.m16n8k16.row.col.f32.bf16.bf16.f32 "
        "{%0,%1,%2,%3}, {%4,%5,%6,%7}, {%8,%9}, {%0,%1,%2,%3};"
        : "+f"(c[0]), "+f"(c[1]), "+f"(c[2]), "+f"(c[3])
        : "r"(a[0]), "r"(a[1]), "r"(a[2]), "r"(a[3]), "r"(b[0]), "r"(b[1]));
}

__device__ __forceinline__ void ldsm4(uint32_t* r, uint32_t addr) {
    asm volatile("ldmatrix.sync.aligned.m8n8.x4.shared.b16 {%0,%1,%2,%3}, [%4];"
        : "=r"(r[0]), "=r"(r[1]), "=r"(r[2]), "=r"(r[3]) : "r"(addr));
}

#define CP_ASYNC16(dst, src) \
    asm volatile("cp.async.ca.shared.global [%0], [%1], 16;" \
                 :: "r"(dst), "l"(src) : "memory")
#define CP_COMMIT()  asm volatile("cp.async.commit_group;" ::: "memory")
#define CP_WAIT1()   asm volatile("cp.async.wait_group 1;" ::: "memory")

__device__ __forceinline__ uint32_t smem_u32(const void* p) {
    uint32_t a;
    asm("{ .reg .u64 t; cvta.to.shared.u64 t, %1; cvt.u32.u64 %0, t; }"
        : "=r"(a) : "l"(p));
    return a;
}

__device__ __forceinline__ void cvt2(float x, float y, uint32_t& hi, uint32_t& lo) {
    __nv_bfloat16 hx = __float2bfloat16_rn(x);
    __nv_bfloat16 hy = __float2bfloat16_rn(y);
    float rx = x - __bfloat162float(hx);
    float ry = y - __bfloat162float(hy);
    __nv_bfloat16 lx = __float2bfloat16_rn(rx);
    __nv_bfloat16 ly = __float2bfloat16_rn(ry);
    hi = (uint32_t)__bfloat16_as_ushort(hx) | ((uint32_t)__bfloat16_as_ushort(hy) << 16);
    lo = (uint32_t)__bfloat16_as_ushort(lx) | ((uint32_t)__bfloat16_as_ushort(ly) << 16);
}

// =====================================================================
// 0) zero accumulators
// =====================================================================
__global__ void k_zero() {
    int i = blockIdx.x * blockDim.x + threadIdx.x;
    if (i < H_) { g_sum[i] = 0.f; g_sumsq[i] = 0.f; }
    if (i < B_ * H_) g_pooled[i] = 0.f;
}

// =====================================================================
// 1) per-batch valid-token counts
// =====================================================================
__global__ void k_counts(const int* __restrict__ mask) {
    __shared__ float red[256];
    int b = blockIdx.x;
    float s = 0.f;
    for (int l = threadIdx.x; l < L_; l += 256)
        s += (float)mask[b * L_ + l];
    red[threadIdx.x] = s;
    __syncthreads();
    for (int o = 128; o > 0; o >>= 1) {
        if (threadIdx.x < o) red[threadIdx.x] += red[threadIdx.x + o];
        __syncthreads();
    }
    if (threadIdx.x == 0) g_counts[b] = red[0];
}

// =====================================================================
// 1b) prep: W1 (D,H) -> transposed bf16 hi/lo (H,D)
// =====================================================================
__global__ void k_prepW1(const float* __restrict__ W1) {
    int idx = blockIdx.x * 256 + threadIdx.x;   // (n, k2) pairs
    if (idx >= H_ * (D_ / 2)) return;
    int n  = idx / (D_ / 2);
    int k2 = idx % (D_ / 2);
    float f0 = W1[(size_t)(2 * k2)     * H_ + n];
    float f1 = W1[(size_t)(2 * k2 + 1) * H_ + n];
    uint32_t ph, pl;
    cvt2(f0, f1, ph, pl);
    ((uint32_t*)g_w1t_hi)[idx] = ph;
    ((uint32_t*)g_w1t_lo)[idx] = pl;
}

// =====================================================================
// 1c) prep: hidden fp32 -> bf16 hi/lo (row-major [M][D])
// =====================================================================
__global__ __launch_bounds__(256) void k_prepA(const float4* __restrict__ A4) {
    int idx = blockIdx.x * 256 + threadIdx.x;
    if (idx >= M_ * D_ / 4) return;
    float4 v = A4[idx];
    uint32_t h0, l0, h1, l1;
    cvt2(v.x, v.y, h0, l0);
    cvt2(v.z, v.w, h1, l1);
    ((uint2*)g_a_hi)[idx] = make_uint2(h0, h1);
    ((uint2*)g_a_lo)[idx] = make_uint2(l0, l1);
}

// =====================================================================
// 2) GEMM1: h = A @ W1 + b1 via mma.sync bf16x3, pure cp.async mainloop
//    CTA 128x128xK64, 512 threads, 16 warps 32x32, 3-stage pipeline
//    Fused: masked BN stats (sum/sumsq) via shfl + atomics
// =====================================================================
#define NCHUNK 12
#define STR    144                 // padded row stride (bytes) for 128B rows
#define ST_AH  0
#define ST_AL  18432
#define ST_BH  36864
#define ST_BL  55296
#define STAGEB 73728
#define SMEM_GEMM (3 * STAGEB)     // 221184 bytes

__global__ __launch_bounds__(512, 1) void k_gemm_mma(
    const int* __restrict__ mask,
    const float* __restrict__ b1)
{
    extern __shared__ uint32_t S[];
    const uint32_t sbase = smem_u32(S);
    const int tid  = threadIdx.x;
    const int lane = tid & 31;
    const int wid  = tid >> 5;        // 0..15
    const int warp_m = wid & 3;       // 4 m-groups of 32 rows
    const int warp_n = wid >> 2;      // 4 n-groups of 32 cols
    const int m0 = blockIdx.y * 128;
    const int n0 = blockIdx.x * 128;

    // loader mapping: 4 threads per row; thread covers 2x16B slices
    const int lrow = tid >> 2;                 // 0..127
    const int sl2  = (tid & 3) * 2;            // slice pair {sl2, sl2+1}
    const char* pAh = (const char*)g_a_hi  + (size_t)(m0 + lrow) * (D_ * 2) + sl2 * 16;
    const char* pAl = (const char*)g_a_lo  + (size_t)(m0 + lrow) * (D_ * 2) + sl2 * 16;
    const char* pBh = (const char*)g_w1t_hi + (size_t)(n0 + lrow) * (D_ * 2) + sl2 * 16;
    const char* pBl = (const char*)g_w1t_lo + (size_t)(n0 + lrow) * (D_ * 2) + sl2 * 16;
    const uint32_t dsto = (uint32_t)lrow * STR + sl2 * 16;

    // fragment ldmatrix base offsets (bytes)
    const uint32_t aoff = (uint32_t)(warp_m * 32 + (lane & 15)) * STR + ((lane >> 4) << 4);
    const uint32_t boff = (uint32_t)(warp_n * 32 + lane) * STR;

    float c[2][4][4];
    #pragma unroll
    for (int i = 0; i < 2; i++)
        #pragma unroll
        for (int j = 0; j < 4; j++)
            #pragma unroll
            for (int q = 0; q < 4; q++) c[i][j][q] = 0.f;

    // ---- prologue: stage chunks 0 and 1 ----
    #pragma unroll
    for (int p = 0; p < 2; ++p) {
        uint32_t d = sbase + p * STAGEB + dsto;
        int off = p * 128;            // 64 bf16 = 128 bytes per chunk
        CP_ASYNC16(d + ST_AH,      pAh + off);
        CP_ASYNC16(d + ST_AH + 16, pAh + off + 16);
        CP_ASYNC16(d + ST_AL,      pAl + off);
        CP_ASYNC16(d + ST_AL + 16, pAl + off + 16);
        CP_ASYNC16(d + ST_BH,      pBh + off);
        CP_ASYNC16(d + ST_BH + 16, pBh + off + 16);
        CP_ASYNC16(d + ST_BL,      pBl + off);
        CP_ASYNC16(d + ST_BL + 16, pBl + off + 16);
        CP_COMMIT();
    }

    int stage = 0, nstage = 2;
    for (int cidx = 0; cidx < NCHUNK; ++cidx) {
        CP_WAIT1();
        __syncthreads();
        if (cidx + 2 < NCHUNK) {
            uint32_t d = sbase + nstage * STAGEB + dsto;
            int off = (cidx + 2) * 128;
            CP_ASYNC16(d + ST_AH,      pAh + off);
            CP_ASYNC16(d + ST_AH + 16, pAh + off + 16);
            CP_ASYNC16(d + ST_AL,      pAl + off);
            CP_ASYNC16(d + ST_AL + 16, pAl + off + 16);
            CP_ASYNC16(d + ST_BH,      pBh + off);
            CP_ASYNC16(d + ST_BH + 16, pBh + off + 16);
            CP_ASYNC16(d + ST_BL,      pBl + off);
            CP_ASYNC16(d + ST_BL + 16, pBl + off + 16);
        }
        CP_COMMIT();

        const uint32_t st = sbase + stage * STAGEB;
        #pragma unroll
        for (int ks = 0; ks < 4; ++ks) {
            const uint32_t kb = ks * 32;
            uint32_t ah[2][4], al[2][4];
            uint32_t bh0[4], bh1[4], bl0[4], bl1[4];
            ldsm4(ah[0], st + ST_AH + aoff + kb);
            ldsm4(ah[1], st + ST_AH + aoff + 16 * STR + kb);
            ldsm4(al[0], st + ST_AL + aoff + kb);
            ldsm4(al[1], st + ST_AL + aoff + 16 * STR + kb);
            ldsm4(bh0, st + ST_BH + boff + kb);
            ldsm4(bh1, st + ST_BH + boff + kb + 16);
            ldsm4(bl0, st + ST_BL + boff + kb);
            ldsm4(bl1, st + ST_BL + boff + kb + 16);
            #pragma unroll
            for (int mi = 0; mi < 2; mi++)
                #pragma unroll
                for (int ni = 0; ni < 4; ni++) {
                    uint32_t bfh[2] = { bh0[ni], bh1[ni] };
                    uint32_t bfl[2] = { bl0[ni], bl1[ni] };
                    mma16816(c[mi][ni], ah[mi], bfh);
                    mma16816(c[mi][ni], ah[mi], bfl);
                    mma16816(c[mi][ni], al[mi], bfh);
                }
        }
        stage = (stage + 1 == 3) ? 0 : stage + 1;
        nstage = (nstage + 1 == 3) ? 0 : nstage + 1;
    }

    // ---- epilogue: + b1, store h, fused masked stats ----
    const int rbase = m0 + warp_m * 32 + (lane >> 2);
    const int cb    = warp_n * 32 + (lane & 3) * 2;
    float mk[4];
    #pragma unroll
    for (int j = 0; j < 4; j++) mk[j] = (float)mask[rbase + j * 8];

    #pragma unroll
    for (int ni = 0; ni < 4; ni++) {
        int col = n0 + cb + ni * 8;
        float2 bb = *(const float2*)&b1[col];
        float h00 = c[0][ni][0] + bb.x, h01 = c[0][ni][1] + bb.y;
        float h02 = c[0][ni][2] + bb.x, h03 = c[0][ni][3] + bb.y;
        float h10 = c[1][ni][0] + bb.x, h11 = c[1][ni][1] + bb.y;
        float h12 = c[1][ni][2] + bb.x, h13 = c[1][ni][3] + bb.y;
        *(float2*)&g_h[(size_t)(rbase     ) * H_ + col] = make_float2(h00, h01);
        *(float2*)&g_h[(size_t)(rbase +  8) * H_ + col] = make_float2(h02, h03);
        *(float2*)&g_h[(size_t)(rbase + 16) * H_ + col] = make_float2(h10, h11);
        *(float2*)&g_h[(size_t)(rbase + 24) * H_ + col] = make_float2(h12, h13);

        float sx = mk[0]*h00 + mk[1]*h02 + mk[2]*h10 + mk[3]*h12;
        float sy = mk[0]*h01 + mk[1]*h03 + mk[2]*h11 + mk[3]*h13;
        float qx = mk[0]*h00*h00 + mk[1]*h02*h02 + mk[2]*h10*h10 + mk[3]*h12*h12;
        float qy = mk[0]*h01*h01 + mk[1]*h03*h03 + mk[2]*h11*h11 + mk[3]*h13*h13;
        #pragma unroll
        for (int o = 4; o < 32; o <<= 1) {
            sx += __shfl_xor_sync(0xffffffffu, sx, o);
            sy += __shfl_xor_sync(0xffffffffu, sy, o);
            qx += __shfl_xor_sync(0xffffffffu, qx, o);
            qy += __shfl_xor_sync(0xffffffffu, qy, o);
        }
        if (lane < 4) {
            atomicAdd(&g_sum[col],       sx);
            atomicAdd(&g_sum[col + 1],   sy);
            atomicAdd(&g_sumsq[col],     qx);
            atomicAdd(&g_sumsq[col + 1], qy);
        }
    }
}

// =====================================================================
// 4) finalize BN affine
// =====================================================================
__global__ void k_finalize(const float* __restrict__ gamma,
                           const float* __restrict__ beta) {
    int tid = threadIdx.x;   // 512 threads
    float nv = 0.f;
    #pragma unroll
    for (int b = 0; b < B_; b++) nv += g_counts[b];
    nv = fmaxf(nv, 1.f);
    float mean = g_sum[tid] / nv;
    float var  = g_sumsq[tid] / nv - mean * mean;
    var = fmaxf(var, 0.f);
    float istd = rsqrtf(var + 1e-5f);
    float sc = istd * gamma[tid];
    g_scale[tid] = sc;
    g_shift[tid] = beta[tid] - mean * sc;
}

// =====================================================================
// 5) masked relu-normalize-pool (float4, MLP=4, branch-free)
// =====================================================================
__global__ __launch_bounds__(128) void k_pool(const int* __restrict__ mask) {
    int tid = threadIdx.x;               // float4 feature group
    int b = blockIdx.y;
    int base = b * L_ + blockIdx.x * 128;
    float4 sc = ((const float4*)g_scale)[tid];
    float4 sh = ((const float4*)g_shift)[tid];
    float4 acc = make_float4(0.f, 0.f, 0.f, 0.f);
    const float4* hp = (const float4*)g_h;
    for (int r = 0; r < 128; r += 4) {
        int4 m4 = *(const int4*)&mask[base + r];
        float mf[4] = {(float)m4.x, (float)m4.y, (float)m4.z, (float)m4.w};
        float4 v[4];
        #pragma unroll
        for (int j = 0; j < 4; j++)
            v[j] = hp[(size_t)(base + r + j) * 128 + tid];
        #pragma unroll
        for (int j = 0; j < 4; j++) {
            acc.x += mf[j] * fmaxf(fmaf(v[j].x, sc.x, sh.x), 0.f);
            acc.y += mf[j] * fmaxf(fmaf(v[j].y, sc.y, sh.y), 0.f);
            acc.z += mf[j] * fmaxf(fmaf(v[j].z, sc.z, sh.z), 0.f);
            acc.w += mf[j] * fmaxf(fmaf(v[j].w, sc.w, sh.w), 0.f);
        }
    }
    int f = b * H_ + tid * 4;
    atomicAdd(&g_pooled[f + 0], acc.x);
    atomicAdd(&g_pooled[f + 1], acc.y);
    atomicAdd(&g_pooled[f + 2], acc.z);
    atomicAdd(&g_pooled[f + 3], acc.w);
}

// =====================================================================
// 6) tiny GEMM2
// =====================================================================
__global__ __launch_bounds__(512) void k_gemm2(
    const float* __restrict__ W2,
    const float* __restrict__ b2,
    float* __restrict__ out)
{
    __shared__ float p[H_];
    int b = blockIdx.x;
    int j = threadIdx.x;
    float cnt = fmaxf(g_counts[b], 1.f);
    p[j] = g_pooled[b * H_ + j] / cnt;
    __syncthreads();
    float acc = b2[j];
    #pragma unroll 8
    for (int h = 0; h < H_; h++)
        acc = fmaf(p[h], W2[(size_t)h * H_ + j], acc);
    out[b * H_ + j] = acc;
}

// =====================================================================
extern "C" void kernel_launch(void* const* d_in, const int* in_sizes, int n_in,
                              void* d_out, int out_size) {
    const float* hidden = (const float*)d_in[0];
    const int*   mask   = (const int*)  d_in[1];
    const float* W1     = (const float*)d_in[2];
    const float* b1     = (const float*)d_in[3];
    const float* gamma  = (const float*)d_in[4];
    const float* beta   = (const float*)d_in[5];
    const float* W2     = (const float*)d_in[6];
    const float* b2     = (const float*)d_in[7];
    float* out = (float*)d_out;

    cudaFuncSetAttribute(k_gemm_mma,
                         cudaFuncAttributeMaxDynamicSharedMemorySize, SMEM_GEMM);

    k_zero<<<64, 256>>>();
    k_counts<<<B_, 256>>>(mask);
    k_prepW1<<<(H_ * (D_ / 2) + 255) / 256, 256>>>(W1);
    k_prepA<<<(M_ * D_ / 4 + 255) / 256, 256>>>((const float4*)hidden);
    dim3 g1(H_ / 128, M_ / 128);                 // (4, 512)
    k_gemm_mma<<<g1, 512, SMEM_GEMM>>>(mask, b1);
    k_finalize<<<1, 512>>>(gamma, beta);
    dim3 gp(16, B_);
    k_pool<<<gp, 128>>>(mask);
    k_gemm2<<<B_, 512>>>(W2, b2, out);
}

// round 8
// speedup vs baseline: 1.1834x; 1.1834x over previous
#include <cuda_runtime.h>
#include <cuda_bf16.h>
#include <cstdint>

#define B_ 32
#define L_ 2048
#define D_ 768
#define H_ 512
#define M_ (B_*L_)   // 65536 tokens

// ---- scratch (__device__ globals per allocation rules) ----
__device__ float g_h[(size_t)M_ * H_];          // 134 MB intermediate h
__device__ __nv_bfloat16 g_w1t_hi[H_ * D_];     // W1 transposed, bf16 hi
__device__ __nv_bfloat16 g_w1t_lo[H_ * D_];     // W1 transposed, bf16 lo
__device__ float g_sum[H_];
__device__ float g_sumsq[H_];
__device__ float g_scale[H_];
__device__ float g_shift[H_];
__device__ float g_counts[B_];
__device__ float g_pooled[B_ * H_];

// =====================================================================
// helpers
// =====================================================================
__device__ __forceinline__ void mma16816(float* c, const uint32_t* a,
                                         const uint32_t* b) {
    asm volatile(
        "mma.sync.aligned.m16n8k16.row.col.f32.bf16.bf16.f32 "
        "{%0,%1,%2,%3}, {%4,%5,%6,%7}, {%8,%9}, {%0,%1,%2,%3};"
        : "+f"(c[0]), "+f"(c[1]), "+f"(c[2]), "+f"(c[3])
        : "r"(a[0]), "r"(a[1]), "r"(a[2]), "r"(a[3]), "r"(b[0]), "r"(b[1]));
}

__device__ __forceinline__ void ldsm4(uint32_t* r, uint32_t addr) {
    asm volatile("ldmatrix.sync.aligned.m8n8.x4.shared.b16 {%0,%1,%2,%3}, [%4];"
        : "=r"(r[0]), "=r"(r[1]), "=r"(r[2]), "=r"(r[3]) : "r"(addr));
}

#define CP_ASYNC16(dst, src) \
    asm volatile("cp.async.ca.shared.global [%0], [%1], 16;" \
                 :: "r"(dst), "l"(src) : "memory")
#define CP_COMMIT()  asm volatile("cp.async.commit_group;" ::: "memory")
#define CP_WAIT0()   asm volatile("cp.async.wait_group 0;" ::: "memory")

__device__ __forceinline__ uint32_t smem_u32(const void* p) {
    uint32_t a;
    asm("{ .reg .u64 t; cvta.to.shared.u64 t, %1; cvt.u32.u64 %0, t; }"
        : "=r"(a) : "l"(p));
    return a;
}

__device__ __forceinline__ void cvt2(float x, float y, uint32_t& hi, uint32_t& lo) {
    __nv_bfloat16 hx = __float2bfloat16_rn(x);
    __nv_bfloat16 hy = __float2bfloat16_rn(y);
    float rx = x - __bfloat162float(hx);
    float ry = y - __bfloat162float(hy);
    __nv_bfloat16 lx = __float2bfloat16_rn(rx);
    __nv_bfloat16 ly = __float2bfloat16_rn(ry);
    hi = (uint32_t)__bfloat16_as_ushort(hx) | ((uint32_t)__bfloat16_as_ushort(hy) << 16);
    lo = (uint32_t)__bfloat16_as_ushort(lx) | ((uint32_t)__bfloat16_as_ushort(ly) << 16);
}

// =====================================================================
// 0) zero accumulators
// =====================================================================
__global__ void k_zero() {
    int i = blockIdx.x * blockDim.x + threadIdx.x;
    if (i < H_) { g_sum[i] = 0.f; g_sumsq[i] = 0.f; }
    if (i < B_ * H_) g_pooled[i] = 0.f;
}

// =====================================================================
// 1) per-batch valid-token counts
// =====================================================================
__global__ void k_counts(const int* __restrict__ mask) {
    __shared__ float red[256];
    int b = blockIdx.x;
    float s = 0.f;
    for (int l = threadIdx.x; l < L_; l += 256)
        s += (float)mask[b * L_ + l];
    red[threadIdx.x] = s;
    __syncthreads();
    for (int o = 128; o > 0; o >>= 1) {
        if (threadIdx.x < o) red[threadIdx.x] += red[threadIdx.x + o];
        __syncthreads();
    }
    if (threadIdx.x == 0) g_counts[b] = red[0];
}

// =====================================================================
// 1b) prep: W1 (D,H) -> transposed bf16 hi/lo (H,D)
// =====================================================================
__global__ void k_prepW1(const float* __restrict__ W1) {
    int idx = blockIdx.x * 256 + threadIdx.x;   // (n, k2) pairs
    if (idx >= H_ * (D_ / 2)) return;
    int n  = idx / (D_ / 2);
    int k2 = idx % (D_ / 2);
    float f0 = W1[(size_t)(2 * k2)     * H_ + n];
    float f1 = W1[(size_t)(2 * k2 + 1) * H_ + n];
    uint32_t ph, pl;
    cvt2(f0, f1, ph, pl);
    ((uint32_t*)g_w1t_hi)[idx] = ph;
    ((uint32_t*)g_w1t_lo)[idx] = pl;
}

// =====================================================================
// 2) GEMM1: h = hidden @ W1 + b1 via mma.sync bf16x3 + ldmatrix
//    CTA tile 128x128x32, 512 threads, 16 warps of 32x32, dbl-buffered
//    Fused epilogue: +b1, store h, masked BN stats via shfl+atomics
// =====================================================================
#define BKC 32
#define NCHUNK (D_ / BKC)       // 24
// SMEM per buffer: rows padded to 40 bf16 (80 B = 20 u32)
// AH 128*80=10240 B, AL, BH, BL  -> 40960 B per buffer
#define BUFB   40960
#define ALOFF  10240
#define BHOFF  20480
#define BLOFF  30720
#define SMEM_GEMM (2 * BUFB)    // 81920 bytes

__global__ __launch_bounds__(512, 1) void k_gemm_mma(
    const float* __restrict__ A,    // hidden (M x D)
    const float* __restrict__ b1,
    const int* __restrict__ mask)
{
    extern __shared__ uint32_t S[];
    const uint32_t sbase = smem_u32(S);
    const int tid  = threadIdx.x;
    const int lane = tid & 31;
    const int wid  = tid >> 5;        // 0..15
    const int warp_m = wid & 3;       // 4 m-groups of 32 rows
    const int warp_n = wid >> 2;      // 4 n-groups of 32 cols
    const int m0 = blockIdx.y * 128;
    const int n0 = blockIdx.x * 128;

    // loader mapping: 4 threads per row, each 8 elements
    const int lr = tid >> 2;          // 0..127
    const int lq = tid & 3;           // 8-element group

    const float4* aglob = (const float4*)(A + (size_t)(m0 + lr) * D_) + lq * 2;
    const __nv_bfloat16* bhg = g_w1t_hi + (size_t)(n0 + lr) * D_ + lq * 8;
    const __nv_bfloat16* blg = g_w1t_lo + (size_t)(n0 + lr) * D_ + lq * 8;
    const uint32_t stoff = lr * 80 + lq * 16;           // byte offset in tile

    // fragment ldmatrix base offsets (bytes)
    const uint32_t aoff = (uint32_t)(warp_m * 32 + (lane & 15)) * 80 + ((lane >> 4) << 4);
    const uint32_t boff = BHOFF + (uint32_t)(warp_n * 32 + lane) * 80;

    float c[2][4][4];
    #pragma unroll
    for (int i = 0; i < 2; i++)
        #pragma unroll
        for (int j = 0; j < 4; j++)
            #pragma unroll
            for (int q = 0; q < 4; q++) c[i][j][q] = 0.f;

    // ---- prologue: load chunk 0 into buffer 0 ----
    {
        CP_ASYNC16(sbase + BHOFF + stoff, bhg);
        CP_ASYNC16(sbase + BLOFF + stoff, blg);
        CP_COMMIT();
        float4 a40 = aglob[0], a41 = aglob[1];
        uint32_t hu[4], lu[4];
        cvt2(a40.x, a40.y, hu[0], lu[0]);
        cvt2(a40.z, a40.w, hu[1], lu[1]);
        cvt2(a41.x, a41.y, hu[2], lu[2]);
        cvt2(a41.z, a41.w, hu[3], lu[3]);
        *(uint4*)((char*)S + stoff)         = make_uint4(hu[0], hu[1], hu[2], hu[3]);
        *(uint4*)((char*)S + ALOFF + stoff) = make_uint4(lu[0], lu[1], lu[2], lu[3]);
        CP_WAIT0();
    }
    __syncthreads();

    for (int cidx = 0; cidx < NCHUNK; ++cidx) {
        const int cur = cidx & 1;
        const int nxt = cur ^ 1;
        float4 a40, a41;
        if (cidx + 1 < NCHUNK) {
            const int kt = (cidx + 1) * BKC;
            CP_ASYNC16(sbase + nxt * BUFB + BHOFF + stoff, bhg + kt);
            CP_ASYNC16(sbase + nxt * BUFB + BLOFF + stoff, blg + kt);
            CP_COMMIT();
            a40 = aglob[(cidx + 1) * 8];
            a41 = aglob[(cidx + 1) * 8 + 1];
        }

        // ---- compute on cur buffer ----
        {
            const uint32_t bufb = sbase + cur * BUFB;
            #pragma unroll
            for (int ks = 0; ks < 2; ++ks) {            // two k16 groups
                const uint32_t kb = ks * 32;
                uint32_t ah[2][4], al[2][4];
                uint32_t bh0[4], bh1[4], bl0[4], bl1[4];
                #pragma unroll
                for (int mi = 0; mi < 2; mi++) {
                    ldsm4(ah[mi], bufb + aoff + mi * 16 * 80 + kb);
                    ldsm4(al[mi], bufb + ALOFF + aoff + mi * 16 * 80 + kb);
                }
                ldsm4(bh0, bufb + boff + kb);
                ldsm4(bh1, bufb + boff + kb + 16);
                ldsm4(bl0, bufb + (BLOFF - BHOFF) + boff + kb);
                ldsm4(bl1, bufb + (BLOFF - BHOFF) + boff + kb + 16);
                #pragma unroll
                for (int mi = 0; mi < 2; mi++)
                    #pragma unroll
                    for (int ni = 0; ni < 4; ni++) {
                        uint32_t bfh[2] = { bh0[ni], bh1[ni] };
                        uint32_t bfl[2] = { bl0[ni], bl1[ni] };
                        mma16816(c[mi][ni], ah[mi], bfh);
                        mma16816(c[mi][ni], ah[mi], bfl);
                        mma16816(c[mi][ni], al[mi], bfh);
                    }
            }
        }

        if (cidx + 1 < NCHUNK) {
            uint32_t hu[4], lu[4];
            cvt2(a40.x, a40.y, hu[0], lu[0]);
            cvt2(a40.z, a40.w, hu[1], lu[1]);
            cvt2(a41.x, a41.y, hu[2], lu[2]);
            cvt2(a41.z, a41.w, hu[3], lu[3]);
            char* bb = (char*)S + nxt * BUFB;
            *(uint4*)(bb + stoff)         = make_uint4(hu[0], hu[1], hu[2], hu[3]);
            *(uint4*)(bb + ALOFF + stoff) = make_uint4(lu[0], lu[1], lu[2], lu[3]);
            CP_WAIT0();
        }
        __syncthreads();
    }

    // ---- epilogue: + b1, store h, fused masked stats ----
    const int rbase = m0 + warp_m * 32 + (lane >> 2);
    const int cb    = warp_n * 32 + (lane & 3) * 2;
    float mk[4];
    #pragma unroll
    for (int j = 0; j < 4; j++) mk[j] = (float)mask[rbase + j * 8];

    #pragma unroll
    for (int ni = 0; ni < 4; ni++) {
        int col = n0 + cb + ni * 8;
        float2 bb = *(const float2*)&b1[col];
        float h00 = c[0][ni][0] + bb.x, h01 = c[0][ni][1] + bb.y;
        float h02 = c[0][ni][2] + bb.x, h03 = c[0][ni][3] + bb.y;
        float h10 = c[1][ni][0] + bb.x, h11 = c[1][ni][1] + bb.y;
        float h12 = c[1][ni][2] + bb.x, h13 = c[1][ni][3] + bb.y;
        *(float2*)&g_h[(size_t)(rbase     ) * H_ + col] = make_float2(h00, h01);
        *(float2*)&g_h[(size_t)(rbase +  8) * H_ + col] = make_float2(h02, h03);
        *(float2*)&g_h[(size_t)(rbase + 16) * H_ + col] = make_float2(h10, h11);
        *(float2*)&g_h[(size_t)(rbase + 24) * H_ + col] = make_float2(h12, h13);

        float sx = mk[0]*h00 + mk[1]*h02 + mk[2]*h10 + mk[3]*h12;
        float sy = mk[0]*h01 + mk[1]*h03 + mk[2]*h11 + mk[3]*h13;
        float qx = mk[0]*h00*h00 + mk[1]*h02*h02 + mk[2]*h10*h10 + mk[3]*h12*h12;
        float qy = mk[0]*h01*h01 + mk[1]*h03*h03 + mk[2]*h11*h11 + mk[3]*h13*h13;
        #pragma unroll
        for (int o = 4; o < 32; o <<= 1) {
            sx += __shfl_xor_sync(0xffffffffu, sx, o);
            sy += __shfl_xor_sync(0xffffffffu, sy, o);
            qx += __shfl_xor_sync(0xffffffffu, qx, o);
            qy += __shfl_xor_sync(0xffffffffu, qy, o);
        }
        if (lane < 4) {
            atomicAdd(&g_sum[col],       sx);
            atomicAdd(&g_sum[col + 1],   sy);
            atomicAdd(&g_sumsq[col],     qx);
            atomicAdd(&g_sumsq[col + 1], qy);
        }
    }
}

// =====================================================================
// 4) finalize BN affine
// =====================================================================
__global__ void k_finalize(const float* __restrict__ gamma,
                           const float* __restrict__ beta) {
    int tid = threadIdx.x;   // 512 threads
    float nv = 0.f;
    #pragma unroll
    for (int b = 0; b < B_; b++) nv += g_counts[b];
    nv = fmaxf(nv, 1.f);
    float mean = g_sum[tid] / nv;
    float var  = g_sumsq[tid] / nv - mean * mean;
    var = fmaxf(var, 0.f);
    float istd = rsqrtf(var + 1e-5f);
    float sc = istd * gamma[tid];
    g_scale[tid] = sc;
    g_shift[tid] = beta[tid] - mean * sc;
}

// =====================================================================
// 5) masked relu-normalize-pool (float4, MLP=4, branch-free)
// =====================================================================
__global__ __launch_bounds__(128) void k_pool(const int* __restrict__ mask) {
    int tid = threadIdx.x;               // float4 feature group
    int b = blockIdx.y;
    int base = b * L_ + blockIdx.x * 128;
    float4 sc = ((const float4*)g_scale)[tid];
    float4 sh = ((const float4*)g_shift)[tid];
    float4 acc = make_float4(0.f, 0.f, 0.f, 0.f);
    const float4* hp = (const float4*)g_h;
    for (int r = 0; r < 128; r += 4) {
        int4 m4 = *(const int4*)&mask[base + r];
        float mf[4] = {(float)m4.x, (float)m4.y, (float)m4.z, (float)m4.w};
        float4 v[4];
        #pragma unroll
        for (int j = 0; j < 4; j++)
            v[j] = hp[(size_t)(base + r + j) * 128 + tid];
        #pragma unroll
        for (int j = 0; j < 4; j++) {
            acc.x += mf[j] * fmaxf(fmaf(v[j].x, sc.x, sh.x), 0.f);
            acc.y += mf[j] * fmaxf(fmaf(v[j].y, sc.y, sh.y), 0.f);
            acc.z += mf[j] * fmaxf(fmaf(v[j].z, sc.z, sh.z), 0.f);
            acc.w += mf[j] * fmaxf(fmaf(v[j].w, sc.w, sh.w), 0.f);
        }
    }
    int f = b * H_ + tid * 4;
    atomicAdd(&g_pooled[f + 0], acc.x);
    atomicAdd(&g_pooled[f + 1], acc.y);
    atomicAdd(&g_pooled[f + 2], acc.z);
    atomicAdd(&g_pooled[f + 3], acc.w);
}

// =====================================================================
// 6) tiny GEMM2
// =====================================================================
__global__ __launch_bounds__(512) void k_gemm2(
    const float* __restrict__ W2,
    const float* __restrict__ b2,
    float* __restrict__ out)
{
    __shared__ float p[H_];
    int b = blockIdx.x;
    int j = threadIdx.x;
    float cnt = fmaxf(g_counts[b], 1.f);
    p[j] = g_pooled[b * H_ + j] / cnt;
    __syncthreads();
    float acc = b2[j];
    #pragma unroll 8
    for (int h = 0; h < H_; h++)
        acc = fmaf(p[h], W2[(size_t)h * H_ + j], acc);
    out[b * H_ + j] = acc;
}

// =====================================================================
extern "C" void kernel_launch(void* const* d_in, const int* in_sizes, int n_in,
                              void* d_out, int out_size) {
    const float* hidden = (const float*)d_in[0];
    const int*   mask   = (const int*)  d_in[1];
    const float* W1     = (const float*)d_in[2];
    const float* b1     = (const float*)d_in[3];
    const float* gamma  = (const float*)d_in[4];
    const float* beta   = (const float*)d_in[5];
    const float* W2     = (const float*)d_in[6];
    const float* b2     = (const float*)d_in[7];
    float* out = (float*)d_out;

    cudaFuncSetAttribute(k_gemm_mma,
                         cudaFuncAttributeMaxDynamicSharedMemorySize, SMEM_GEMM);

    k_zero<<<64, 256>>>();
    k_counts<<<B_, 256>>>(mask);
    k_prepW1<<<(H_ * (D_ / 2) + 255) / 256, 256>>>(W1);
    dim3 g1(H_ / 128, M_ / 128);                 // (4, 512)
    k_gemm_mma<<<g1, 512, SMEM_GEMM>>>(hidden, b1, mask);
    k_finalize<<<1, 512>>>(gamma, beta);
    dim3 gp(16, B_);
    k_pool<<<gp, 128>>>(mask);
    k_gemm2<<<B_, 512>>>(W2, b2, out);
}

// round 9
// speedup vs baseline: 1.2446x; 1.0518x over previous
#include <cuda_runtime.h>
#include <cuda_bf16.h>
#include <cstdint>

#define B_ 32
#define L_ 2048
#define D_ 768
#define H_ 512
#define M_ (B_*L_)   // 65536 tokens

// ---- scratch (__device__ globals per allocation rules) ----
__device__ float g_h[(size_t)M_ * H_];          // 134 MB intermediate h
__device__ __nv_bfloat16 g_w1t_hi[H_ * D_];     // W1 transposed, bf16 hi
__device__ __nv_bfloat16 g_w1t_lo[H_ * D_];     // W1 transposed, bf16 lo
__device__ float g_sum[H_];
__device__ float g_sumsq[H_];
__device__ float g_scale[H_];
__device__ float g_shift[H_];
__device__ float g_counts[B_];
__device__ float g_pooled[B_ * H_];

// =====================================================================
// helpers
// =====================================================================
__device__ __forceinline__ void mma16816(float* c, const uint32_t* a,
                                         const uint32_t* b) {
    asm volatile(
        "mma.sync.aligned.m16n8k16.row.col.f32.bf16.bf16.f32 "
        "{%0,%1,%2,%3}, {%4,%5,%6,%7}, {%8,%9}, {%0,%1,%2,%3};"
        : "+f"(c[0]), "+f"(c[1]), "+f"(c[2]), "+f"(c[3])
        : "r"(a[0]), "r"(a[1]), "r"(a[2]), "r"(a[3]), "r"(b[0]), "r"(b[1]));
}

__device__ __forceinline__ void ldsm4(uint32_t* r, uint32_t addr) {
    asm volatile("ldmatrix.sync.aligned.m8n8.x4.shared.b16 {%0,%1,%2,%3}, [%4];"
        : "=r"(r[0]), "=r"(r[1]), "=r"(r[2]), "=r"(r[3]) : "r"(addr));
}

#define CP_ASYNC16(dst, src) \
    asm volatile("cp.async.ca.shared.global [%0], [%1], 16;" \
                 :: "r"(dst), "l"(src) : "memory")
#define CP_COMMIT()  asm volatile("cp.async.commit_group;" ::: "memory")
#define CP_WAIT0()   asm volatile("cp.async.wait_group 0;" ::: "memory")

__device__ __forceinline__ uint32_t smem_u32(const void* p) {
    uint32_t a;
    asm("{ .reg .u64 t; cvta.to.shared.u64 t, %1; cvt.u32.u64 %0, t; }"
        : "=r"(a) : "l"(p));
    return a;
}

__device__ __forceinline__ void cvt2(float x, float y, uint32_t& hi, uint32_t& lo) {
    __nv_bfloat16 hx = __float2bfloat16_rn(x);
    __nv_bfloat16 hy = __float2bfloat16_rn(y);
    float rx = x - __bfloat162float(hx);
    float ry = y - __bfloat162float(hy);
    __nv_bfloat16 lx = __float2bfloat16_rn(rx);
    __nv_bfloat16 ly = __float2bfloat16_rn(ry);
    hi = (uint32_t)__bfloat16_as_ushort(hx) | ((uint32_t)__bfloat16_as_ushort(hy) << 16);
    lo = (uint32_t)__bfloat16_as_ushort(lx) | ((uint32_t)__bfloat16_as_ushort(ly) << 16);
}

// =====================================================================
// 0) zero accumulators
// =====================================================================
__global__ void k_zero() {
    int i = blockIdx.x * blockDim.x + threadIdx.x;
    if (i < H_) { g_sum[i] = 0.f; g_sumsq[i] = 0.f; }
    if (i < B_ * H_) g_pooled[i] = 0.f;
}

// =====================================================================
// 1) per-batch valid-token counts
// =====================================================================
__global__ void k_counts(const int* __restrict__ mask) {
    __shared__ float red[256];
    int b = blockIdx.x;
    float s = 0.f;
    for (int l = threadIdx.x; l < L_; l += 256)
        s += (float)mask[b * L_ + l];
    red[threadIdx.x] = s;
    __syncthreads();
    for (int o = 128; o > 0; o >>= 1) {
        if (threadIdx.x < o) red[threadIdx.x] += red[threadIdx.x + o];
        __syncthreads();
    }
    if (threadIdx.x == 0) g_counts[b] = red[0];
}

// =====================================================================
// 1b) prep: W1 (D,H) -> transposed bf16 hi/lo (H,D)
// =====================================================================
__global__ void k_prepW1(const float* __restrict__ W1) {
    int idx = blockIdx.x * 256 + threadIdx.x;   // (n, k2) pairs
    if (idx >= H_ * (D_ / 2)) return;
    int n  = idx / (D_ / 2);
    int k2 = idx % (D_ / 2);
    float f0 = W1[(size_t)(2 * k2)     * H_ + n];
    float f1 = W1[(size_t)(2 * k2 + 1) * H_ + n];
    uint32_t ph, pl;
    cvt2(f0, f1, ph, pl);
    ((uint32_t*)g_w1t_hi)[idx] = ph;
    ((uint32_t*)g_w1t_lo)[idx] = pl;
}

// =====================================================================
// 2) GEMM1: h = hidden @ W1 + b1 via mma.sync bf16x3 + ldmatrix
//    CTA tile 128x128x32, 256 threads, 8 warps of 64x32, dbl-buffered,
//    2 CTAs/SM. Fused epilogue: +b1, store h, masked BN stats.
// =====================================================================
#define BKC 32
#define NCHUNK (D_ / BKC)       // 24
// SMEM per buffer: rows padded to 40 bf16 (80 B = 20 u32)
// AH 128*80=10240 B, AL, BH, BL  -> 40960 B per buffer
#define BUFB   40960
#define ALOFF  10240
#define BHOFF  20480
#define BLOFF  30720
#define SMEM_GEMM (2 * BUFB)    // 81920 bytes

__global__ __launch_bounds__(256, 2) void k_gemm_mma(
    const float* __restrict__ A,    // hidden (M x D)
    const float* __restrict__ b1,
    const int* __restrict__ mask)
{
    extern __shared__ uint32_t S[];
    const uint32_t sbase = smem_u32(S);
    const int tid  = threadIdx.x;
    const int lane = tid & 31;
    const int wid  = tid >> 5;        // 0..7
    const int warp_m = wid & 1;       // 2 m-groups of 64 rows
    const int warp_n = wid >> 1;      // 4 n-groups of 32 cols
    const int m0 = blockIdx.y * 128;
    const int n0 = blockIdx.x * 128;

    // loader mapping: 2 threads per row, each 16 elements
    const int lr = tid >> 1;          // 0..127
    const int lh = tid & 1;           // 16-element half

    const float4* aglob = (const float4*)(A + (size_t)(m0 + lr) * D_) + lh * 4;
    const __nv_bfloat16* bhg = g_w1t_hi + (size_t)(n0 + lr) * D_ + lh * 16;
    const __nv_bfloat16* blg = g_w1t_lo + (size_t)(n0 + lr) * D_ + lh * 16;
    const uint32_t stoff = lr * 80 + lh * 32;           // byte offset in tile

    // fragment ldmatrix base offsets (bytes)
    const uint32_t aoff = (uint32_t)(warp_m * 64 + (lane & 15)) * 80 + ((lane >> 4) << 4);
    const uint32_t boff = BHOFF + (uint32_t)(warp_n * 32 + lane) * 80;

    float c[4][4][4];
    #pragma unroll
    for (int i = 0; i < 4; i++)
        #pragma unroll
        for (int j = 0; j < 4; j++)
            #pragma unroll
            for (int q = 0; q < 4; q++) c[i][j][q] = 0.f;

    // ---- prologue: load chunk 0 into buffer 0 ----
    {
        CP_ASYNC16(sbase + BHOFF + stoff,      bhg);
        CP_ASYNC16(sbase + BHOFF + stoff + 16, bhg + 8);
        CP_ASYNC16(sbase + BLOFF + stoff,      blg);
        CP_ASYNC16(sbase + BLOFF + stoff + 16, blg + 8);
        CP_COMMIT();
        float4 a4[4];
        #pragma unroll
        for (int i = 0; i < 4; i++) a4[i] = aglob[i];
        uint32_t hu[8], lu[8];
        #pragma unroll
        for (int i = 0; i < 4; i++) {
            cvt2(a4[i].x, a4[i].y, hu[2*i],   lu[2*i]);
            cvt2(a4[i].z, a4[i].w, hu[2*i+1], lu[2*i+1]);
        }
        *(uint4*)((char*)S + stoff)              = make_uint4(hu[0], hu[1], hu[2], hu[3]);
        *(uint4*)((char*)S + stoff + 16)         = make_uint4(hu[4], hu[5], hu[6], hu[7]);
        *(uint4*)((char*)S + ALOFF + stoff)      = make_uint4(lu[0], lu[1], lu[2], lu[3]);
        *(uint4*)((char*)S + ALOFF + stoff + 16) = make_uint4(lu[4], lu[5], lu[6], lu[7]);
        CP_WAIT0();
    }
    __syncthreads();

    for (int cidx = 0; cidx < NCHUNK; ++cidx) {
        const int cur = cidx & 1;
        const int nxt = cur ^ 1;
        float4 a4[4];
        if (cidx + 1 < NCHUNK) {
            const int kt = (cidx + 1) * BKC;
            const uint32_t nb = sbase + nxt * BUFB;
            CP_ASYNC16(nb + BHOFF + stoff,      bhg + kt);
            CP_ASYNC16(nb + BHOFF + stoff + 16, bhg + kt + 8);
            CP_ASYNC16(nb + BLOFF + stoff,      blg + kt);
            CP_ASYNC16(nb + BLOFF + stoff + 16, blg + kt + 8);
            CP_COMMIT();
            #pragma unroll
            for (int i = 0; i < 4; i++) a4[i] = aglob[(cidx + 1) * 8 + i];
        }

        // ---- compute on cur buffer ----
        {
            const uint32_t bufb = sbase + cur * BUFB;
            #pragma unroll
            for (int ks = 0; ks < 2; ++ks) {            // two k16 groups
                const uint32_t kb = ks * 32;
                uint32_t ah[4][4], al[4][4];
                uint32_t bh0[4], bh1[4], bl0[4], bl1[4];
                #pragma unroll
                for (int mi = 0; mi < 4; mi++) {
                    ldsm4(ah[mi], bufb + aoff + mi * 16 * 80 + kb);
                    ldsm4(al[mi], bufb + ALOFF + aoff + mi * 16 * 80 + kb);
                }
                ldsm4(bh0, bufb + boff + kb);
                ldsm4(bh1, bufb + boff + kb + 16);
                ldsm4(bl0, bufb + (BLOFF - BHOFF) + boff + kb);
                ldsm4(bl1, bufb + (BLOFF - BHOFF) + boff + kb + 16);
                #pragma unroll
                for (int mi = 0; mi < 4; mi++)
                    #pragma unroll
                    for (int ni = 0; ni < 4; ni++) {
                        uint32_t bfh[2] = { bh0[ni], bh1[ni] };
                        uint32_t bfl[2] = { bl0[ni], bl1[ni] };
                        mma16816(c[mi][ni], ah[mi], bfh);
                        mma16816(c[mi][ni], ah[mi], bfl);
                        mma16816(c[mi][ni], al[mi], bfh);
                    }
            }
        }

        if (cidx + 1 < NCHUNK) {
            uint32_t hu[8], lu[8];
            #pragma unroll
            for (int i = 0; i < 4; i++) {
                cvt2(a4[i].x, a4[i].y, hu[2*i],   lu[2*i]);
                cvt2(a4[i].z, a4[i].w, hu[2*i+1], lu[2*i+1]);
            }
            char* bb = (char*)S + nxt * BUFB;
            *(uint4*)(bb + stoff)              = make_uint4(hu[0], hu[1], hu[2], hu[3]);
            *(uint4*)(bb + stoff + 16)         = make_uint4(hu[4], hu[5], hu[6], hu[7]);
            *(uint4*)(bb + ALOFF + stoff)      = make_uint4(lu[0], lu[1], lu[2], lu[3]);
            *(uint4*)(bb + ALOFF + stoff + 16) = make_uint4(lu[4], lu[5], lu[6], lu[7]);
            CP_WAIT0();
        }
        __syncthreads();
    }

    // ---- epilogue: + b1, store h, fused masked stats ----
    const int rbase = m0 + warp_m * 64 + (lane >> 2);
    const int cb    = warp_n * 32 + (lane & 3) * 2;
    float mk[8];
    #pragma unroll
    for (int mi = 0; mi < 4; mi++) {
        mk[2*mi]   = (float)mask[rbase + mi * 16];
        mk[2*mi+1] = (float)mask[rbase + mi * 16 + 8];
    }

    #pragma unroll
    for (int ni = 0; ni < 4; ni++) {
        int col = n0 + cb + ni * 8;
        float2 bb = *(const float2*)&b1[col];
        float sx = 0.f, sy = 0.f, qx = 0.f, qy = 0.f;
        #pragma unroll
        for (int mi = 0; mi < 4; mi++) {
            int r0 = rbase + mi * 16;
            float h0 = c[mi][ni][0] + bb.x, h1 = c[mi][ni][1] + bb.y;
            float h2 = c[mi][ni][2] + bb.x, h3 = c[mi][ni][3] + bb.y;
            *(float2*)&g_h[(size_t)r0 * H_ + col]       = make_float2(h0, h1);
            *(float2*)&g_h[(size_t)(r0 + 8) * H_ + col] = make_float2(h2, h3);
            sx += mk[2*mi] * h0 + mk[2*mi+1] * h2;
            sy += mk[2*mi] * h1 + mk[2*mi+1] * h3;
            qx += mk[2*mi] * h0 * h0 + mk[2*mi+1] * h2 * h2;
            qy += mk[2*mi] * h1 * h1 + mk[2*mi+1] * h3 * h3;
        }
        #pragma unroll
        for (int o = 4; o < 32; o <<= 1) {
            sx += __shfl_xor_sync(0xffffffffu, sx, o);
            sy += __shfl_xor_sync(0xffffffffu, sy, o);
            qx += __shfl_xor_sync(0xffffffffu, qx, o);
            qy += __shfl_xor_sync(0xffffffffu, qy, o);
        }
        if (lane < 4) {
            atomicAdd(&g_sum[col],       sx);
            atomicAdd(&g_sum[col + 1],   sy);
            atomicAdd(&g_sumsq[col],     qx);
            atomicAdd(&g_sumsq[col + 1], qy);
        }
    }
}

// =====================================================================
// 4) finalize BN affine
// =====================================================================
__global__ void k_finalize(const float* __restrict__ gamma,
                           const float* __restrict__ beta) {
    int tid = threadIdx.x;   // 512 threads
    float nv = 0.f;
    #pragma unroll
    for (int b = 0; b < B_; b++) nv += g_counts[b];
    nv = fmaxf(nv, 1.f);
    float mean = g_sum[tid] / nv;
    float var  = g_sumsq[tid] / nv - mean * mean;
    var = fmaxf(var, 0.f);
    float istd = rsqrtf(var + 1e-5f);
    float sc = istd * gamma[tid];
    g_scale[tid] = sc;
    g_shift[tid] = beta[tid] - mean * sc;
}

// =====================================================================
// 5) masked relu-normalize-pool (float4, MLP=4, branch-free)
// =====================================================================
__global__ __launch_bounds__(128) void k_pool(const int* __restrict__ mask) {
    int tid = threadIdx.x;               // float4 feature group
    int b = blockIdx.y;
    int base = b * L_ + blockIdx.x * 128;
    float4 sc = ((const float4*)g_scale)[tid];
    float4 sh = ((const float4*)g_shift)[tid];
    float4 acc = make_float4(0.f, 0.f, 0.f, 0.f);
    const float4* hp = (const float4*)g_h;
    for (int r = 0; r < 128; r += 4) {
        int4 m4 = *(const int4*)&mask[base + r];
        float mf[4] = {(float)m4.x, (float)m4.y, (float)m4.z, (float)m4.w};
        float4 v[4];
        #pragma unroll
        for (int j = 0; j < 4; j++)
            v[j] = hp[(size_t)(base + r + j) * 128 + tid];
        #pragma unroll
        for (int j = 0; j < 4; j++) {
            acc.x += mf[j] * fmaxf(fmaf(v[j].x, sc.x, sh.x), 0.f);
            acc.y += mf[j] * fmaxf(fmaf(v[j].y, sc.y, sh.y), 0.f);
            acc.z += mf[j] * fmaxf(fmaf(v[j].z, sc.z, sh.z), 0.f);
            acc.w += mf[j] * fmaxf(fmaf(v[j].w, sc.w, sh.w), 0.f);
        }
    }
    int f = b * H_ + tid * 4;
    atomicAdd(&g_pooled[f + 0], acc.x);
    atomicAdd(&g_pooled[f + 1], acc.y);
    atomicAdd(&g_pooled[f + 2], acc.z);
    atomicAdd(&g_pooled[f + 3], acc.w);
}

// =====================================================================
// 6) tiny GEMM2
// =====================================================================
__global__ __launch_bounds__(512) void k_gemm2(
    const float* __restrict__ W2,
    const float* __restrict__ b2,
    float* __restrict__ out)
{
    __shared__ float p[H_];
    int b = blockIdx.x;
    int j = threadIdx.x;
    float cnt = fmaxf(g_counts[b], 1.f);
    p[j] = g_pooled[b * H_ + j] / cnt;
    __syncthreads();
    float acc = b2[j];
    #pragma unroll 8
    for (int h = 0; h < H_; h++)
        acc = fmaf(p[h], W2[(size_t)h * H_ + j], acc);
    out[b * H_ + j] = acc;
}

// =====================================================================
extern "C" void kernel_launch(void* const* d_in, const int* in_sizes, int n_in,
                              void* d_out, int out_size) {
    const float* hidden = (const float*)d_in[0];
    const int*   mask   = (const int*)  d_in[1];
    const float* W1     = (const float*)d_in[2];
    const float* b1     = (const float*)d_in[3];
    const float* gamma  = (const float*)d_in[4];
    const float* beta   = (const float*)d_in[5];
    const float* W2     = (const float*)d_in[6];
    const float* b2     = (const float*)d_in[7];
    float* out = (float*)d_out;

    cudaFuncSetAttribute(k_gemm_mma,
                         cudaFuncAttributeMaxDynamicSharedMemorySize, SMEM_GEMM);

    k_zero<<<64, 256>>>();
    k_counts<<<B_, 256>>>(mask);
    k_prepW1<<<(H_ * (D_ / 2) + 255) / 256, 256>>>(W1);
    dim3 g1(H_ / 128, M_ / 128);                 // (4, 512)
    k_gemm_mma<<<g1, 256, SMEM_GEMM>>>(hidden, b1, mask);
    k_finalize<<<1, 512>>>(gamma, beta);
    dim3 gp(16, B_);
    k_pool<<<gp, 128>>>(mask);
    k_gemm2<<<B_, 512>>>(W2, b2, out);
}

// round 14
// speedup vs baseline: 2.0280x; 1.6294x over previous
#include <cuda_runtime.h>
#include <cuda_fp16.h>
#include <cstdint>

#define B_ 32
#define L_ 2048
#define D_ 768
#define H_ 512
#define M_ (B_*L_)   // 65536 tokens

// ---- scratch (__device__ globals per allocation rules) ----
__device__ __half g_h[(size_t)M_ * H_];         // 67 MB intermediate h (fp16)
__device__ __half g_w1t[H_ * D_];               // W1 transposed, fp16
__device__ float g_sum[H_];
__device__ float g_sumsq[H_];
__device__ float g_scale[H_];
__device__ float g_shift[H_];
__device__ float g_counts[B_];
__device__ float g_pooled[B_ * H_];

// =====================================================================
// helpers
// =====================================================================
__device__ __forceinline__ void mma16816(float* c, const uint32_t* a,
                                         const uint32_t* b) {
    asm volatile(
        "mma.sync.aligned.m16n8k16.row.col.f32.f16.f16.f32 "
        "{%0,%1,%2,%3}, {%4,%5,%6,%7}, {%8,%9}, {%0,%1,%2,%3};"
        : "+f"(c[0]), "+f"(c[1]), "+f"(c[2]), "+f"(c[3])
        : "r"(a[0]), "r"(a[1]), "r"(a[2]), "r"(a[3]), "r"(b[0]), "r"(b[1]));
}

__device__ __forceinline__ void ldsm4(uint32_t* r, uint32_t addr) {
    asm volatile("ldmatrix.sync.aligned.m8n8.x4.shared.b16 {%0,%1,%2,%3}, [%4];"
        : "=r"(r[0]), "=r"(r[1]), "=r"(r[2]), "=r"(r[3]) : "r"(addr));
}

#define CP_ASYNC16(dst, src) \
    asm volatile("cp.async.ca.shared.global [%0], [%1], 16;" \
                 :: "r"(dst), "l"(src) : "memory")
#define CP_COMMIT()  asm volatile("cp.async.commit_group;" ::: "memory")
#define CP_WAIT0()   asm volatile("cp.async.wait_group 0;" ::: "memory")

__device__ __forceinline__ uint32_t smem_u32(const void* p) {
    uint32_t a;
    asm("{ .reg .u64 t; cvta.to.shared.u64 t, %1; cvt.u32.u64 %0, t; }"
        : "=r"(a) : "l"(p));
    return a;
}

__device__ __forceinline__ uint32_t f22u(float x, float y) {
    __half2 h = __floats2half2_rn(x, y);
    return *(uint32_t*)&h;
}

// =====================================================================
// 0) zero accumulators
// =====================================================================
__global__ void k_zero() {
    int i = blockIdx.x * blockDim.x + threadIdx.x;
    if (i < H_) { g_sum[i] = 0.f; g_sumsq[i] = 0.f; }
    if (i < B_ * H_) g_pooled[i] = 0.f;
}

// =====================================================================
// 1) per-batch valid-token counts
// =====================================================================
__global__ void k_counts(const int* __restrict__ mask) {
    __shared__ float red[256];
    int b = blockIdx.x;
    float s = 0.f;
    for (int l = threadIdx.x; l < L_; l += 256)
        s += (float)mask[b * L_ + l];
    red[threadIdx.x] = s;
    __syncthreads();
    for (int o = 128; o > 0; o >>= 1) {
        if (threadIdx.x < o) red[threadIdx.x] += red[threadIdx.x + o];
        __syncthreads();
    }
    if (threadIdx.x == 0) g_counts[b] = red[0];
}

// =====================================================================
// 1b) prep: W1 (D,H) -> transposed fp16 (H,D)
// =====================================================================
__global__ void k_prepW1(const float* __restrict__ W1) {
    int idx = blockIdx.x * 256 + threadIdx.x;   // (n, k2) pairs
    if (idx >= H_ * (D_ / 2)) return;
    int n  = idx / (D_ / 2);
    int k2 = idx % (D_ / 2);
    float f0 = W1[(size_t)(2 * k2)     * H_ + n];
    float f1 = W1[(size_t)(2 * k2 + 1) * H_ + n];
    ((uint32_t*)g_w1t)[idx] = f22u(f0, f1);
}

// =====================================================================
// 2) GEMM1: h = hidden @ W1 + b1 via single fp16 mma.sync + ldmatrix
//    CTA tile 128x128x32, 256 threads, 8 warps of 64x32, dbl-buffered,
//    2 CTAs/SM. Fused epilogue: +b1, store h (fp16), masked BN stats.
// =====================================================================
#define BKC 32
#define NCHUNK (D_ / BKC)       // 24
// SMEM per buffer: rows padded to 80 B (64 B data + 16 pad)
// A 128*80=10240 B, B 128*80=10240 B -> 20480 B per buffer
#define BUFB   20480
#define BOFF   10240
#define SMEM_GEMM (2 * BUFB)    // 40960 bytes

__global__ __launch_bounds__(256, 2) void k_gemm_mma(
    const float* __restrict__ A,    // hidden (M x D)
    const float* __restrict__ b1,
    const int* __restrict__ mask)
{
    extern __shared__ uint32_t S[];
    const uint32_t sbase = smem_u32(S);
    const int tid  = threadIdx.x;
    const int lane = tid & 31;
    const int wid  = tid >> 5;        // 0..7
    const int warp_m = wid & 1;       // 2 m-groups of 64 rows
    const int warp_n = wid >> 1;      // 4 n-groups of 32 cols
    const int m0 = blockIdx.y * 128;
    const int n0 = blockIdx.x * 128;

    // loader mapping: 2 threads per row, each 16 elements
    const int lr = tid >> 1;          // 0..127
    const int lh = tid & 1;           // 16-element half

    const float4* aglob = (const float4*)(A + (size_t)(m0 + lr) * D_) + lh * 4;
    const __half* bg = g_w1t + (size_t)(n0 + lr) * D_ + lh * 16;
    const uint32_t stoff = lr * 80 + lh * 32;           // byte offset in tile

    // fragment ldmatrix base offsets (bytes)
    const uint32_t aoff = (uint32_t)(warp_m * 64 + (lane & 15)) * 80 + ((lane >> 4) << 4);
    const uint32_t boff = BOFF + (uint32_t)(warp_n * 32 + lane) * 80;

    float c[4][4][4];
    #pragma unroll
    for (int i = 0; i < 4; i++)
        #pragma unroll
        for (int j = 0; j < 4; j++)
            #pragma unroll
            for (int q = 0; q < 4; q++) c[i][j][q] = 0.f;

    // ---- prologue: load chunk 0 into buffer 0 ----
    {
        CP_ASYNC16(sbase + BOFF + stoff,      bg);
        CP_ASYNC16(sbase + BOFF + stoff + 16, bg + 8);
        CP_COMMIT();
        float4 a4[4];
        #pragma unroll
        for (int i = 0; i < 4; i++) a4[i] = aglob[i];
        uint32_t hu[8];
        #pragma unroll
        for (int i = 0; i < 4; i++) {
            hu[2*i]   = f22u(a4[i].x, a4[i].y);
            hu[2*i+1] = f22u(a4[i].z, a4[i].w);
        }
        *(uint4*)((char*)S + stoff)      = make_uint4(hu[0], hu[1], hu[2], hu[3]);
        *(uint4*)((char*)S + stoff + 16) = make_uint4(hu[4], hu[5], hu[6], hu[7]);
        CP_WAIT0();
    }
    __syncthreads();

    for (int cidx = 0; cidx < NCHUNK; ++cidx) {
        const int cur = cidx & 1;
        const int nxt = cur ^ 1;
        float4 a4[4];
        if (cidx + 1 < NCHUNK) {
            const int kt = (cidx + 1) * BKC;
            const uint32_t nb = sbase + nxt * BUFB;
            CP_ASYNC16(nb + BOFF + stoff,      bg + kt);
            CP_ASYNC16(nb + BOFF + stoff + 16, bg + kt + 8);
            CP_COMMIT();
            #pragma unroll
            for (int i = 0; i < 4; i++) a4[i] = aglob[(cidx + 1) * 8 + i];
        }

        // ---- compute on cur buffer ----
        {
            const uint32_t bufb = sbase + cur * BUFB;
            #pragma unroll
            for (int ks = 0; ks < 2; ++ks) {            // two k16 groups
                const uint32_t kb = ks * 32;
                uint32_t ah[4][4];
                uint32_t bh0[4], bh1[4];
                #pragma unroll
                for (int mi = 0; mi < 4; mi++)
                    ldsm4(ah[mi], bufb + aoff + mi * 16 * 80 + kb);
                ldsm4(bh0, bufb + boff + kb);
                ldsm4(bh1, bufb + boff + kb + 16);
                #pragma unroll
                for (int mi = 0; mi < 4; mi++)
                    #pragma unroll
                    for (int ni = 0; ni < 4; ni++) {
                        uint32_t bf[2] = { bh0[ni], bh1[ni] };
                        mma16816(c[mi][ni], ah[mi], bf);
                    }
            }
        }

        if (cidx + 1 < NCHUNK) {
            uint32_t hu[8];
            #pragma unroll
            for (int i = 0; i < 4; i++) {
                hu[2*i]   = f22u(a4[i].x, a4[i].y);
                hu[2*i+1] = f22u(a4[i].z, a4[i].w);
            }
            char* bb = (char*)S + nxt * BUFB;
            *(uint4*)(bb + stoff)      = make_uint4(hu[0], hu[1], hu[2], hu[3]);
            *(uint4*)(bb + stoff + 16) = make_uint4(hu[4], hu[5], hu[6], hu[7]);
            CP_WAIT0();
        }
        __syncthreads();
    }

    // ---- epilogue: + b1, store h (fp16), fused masked stats ----
    const int rbase = m0 + warp_m * 64 + (lane >> 2);
    const int cb    = warp_n * 32 + (lane & 3) * 2;
    float mk[8];
    #pragma unroll
    for (int mi = 0; mi < 4; mi++) {
        mk[2*mi]   = (float)mask[rbase + mi * 16];
        mk[2*mi+1] = (float)mask[rbase + mi * 16 + 8];
    }

    #pragma unroll
    for (int ni = 0; ni < 4; ni++) {
        int col = n0 + cb + ni * 8;
        float2 bb = *(const float2*)&b1[col];
        float sx = 0.f, sy = 0.f, qx = 0.f, qy = 0.f;
        #pragma unroll
        for (int mi = 0; mi < 4; mi++) {
            int r0 = rbase + mi * 16;
            float h0 = c[mi][ni][0] + bb.x, h1 = c[mi][ni][1] + bb.y;
            float h2 = c[mi][ni][2] + bb.x, h3 = c[mi][ni][3] + bb.y;
            *(__half2*)&g_h[(size_t)r0 * H_ + col]       = __floats2half2_rn(h0, h1);
            *(__half2*)&g_h[(size_t)(r0 + 8) * H_ + col] = __floats2half2_rn(h2, h3);
            sx += mk[2*mi] * h0 + mk[2*mi+1] * h2;
            sy += mk[2*mi] * h1 + mk[2*mi+1] * h3;
            qx += mk[2*mi] * h0 * h0 + mk[2*mi+1] * h2 * h2;
            qy += mk[2*mi] * h1 * h1 + mk[2*mi+1] * h3 * h3;
        }
        #pragma unroll
        for (int o = 4; o < 32; o <<= 1) {
            sx += __shfl_xor_sync(0xffffffffu, sx, o);
            sy += __shfl_xor_sync(0xffffffffu, sy, o);
            qx += __shfl_xor_sync(0xffffffffu, qx, o);
            qy += __shfl_xor_sync(0xffffffffu, qy, o);
        }
        if (lane < 4) {
            atomicAdd(&g_sum[col],       sx);
            atomicAdd(&g_sum[col + 1],   sy);
            atomicAdd(&g_sumsq[col],     qx);
            atomicAdd(&g_sumsq[col + 1], qy);
        }
    }
}

// =====================================================================
// 4) finalize BN affine
// =====================================================================
__global__ void k_finalize(const float* __restrict__ gamma,
                           const float* __restrict__ beta) {
    int tid = threadIdx.x;   // 512 threads
    float nv = 0.f;
    #pragma unroll
    for (int b = 0; b < B_; b++) nv += g_counts[b];
    nv = fmaxf(nv, 1.f);
    float mean = g_sum[tid] / nv;
    float var  = g_sumsq[tid] / nv - mean * mean;
    var = fmaxf(var, 0.f);
    float istd = rsqrtf(var + 1e-5f);
    float sc = istd * gamma[tid];
    g_scale[tid] = sc;
    g_shift[tid] = beta[tid] - mean * sc;
}

// =====================================================================
// 5) masked relu-normalize-pool (fp16 h, branch-free)
// =====================================================================
__global__ __launch_bounds__(128) void k_pool(const int* __restrict__ mask) {
    int tid = threadIdx.x;               // 4-feature group 0..127
    int b = blockIdx.y;
    int base = b * L_ + blockIdx.x * 128;
    float4 sc = ((const float4*)g_scale)[tid];
    float4 sh = ((const float4*)g_shift)[tid];
    float4 acc = make_float4(0.f, 0.f, 0.f, 0.f);
    const uint2* hp = (const uint2*)g_h;     // 4 fp16 per uint2
    for (int r = 0; r < 128; r += 4) {
        int4 m4 = *(const int4*)&mask[base + r];
        float mf[4] = {(float)m4.x, (float)m4.y, (float)m4.z, (float)m4.w};
        uint2 v[4];
        #pragma unroll
        for (int j = 0; j < 4; j++)
            v[j] = hp[(size_t)(base + r + j) * 128 + tid];
        #pragma unroll
        for (int j = 0; j < 4; j++) {
            float2 p0 = __half22float2(*(__half2*)&v[j].x);
            float2 p1 = __half22float2(*(__half2*)&v[j].y);
            acc.x += mf[j] * fmaxf(fmaf(p0.x, sc.x, sh.x), 0.f);
            acc.y += mf[j] * fmaxf(fmaf(p0.y, sc.y, sh.y), 0.f);
            acc.z += mf[j] * fmaxf(fmaf(p1.x, sc.z, sh.z), 0.f);
            acc.w += mf[j] * fmaxf(fmaf(p1.y, sc.w, sh.w), 0.f);
        }
    }
    int f = b * H_ + tid * 4;
    atomicAdd(&g_pooled[f + 0], acc.x);
    atomicAdd(&g_pooled[f + 1], acc.y);
    atomicAdd(&g_pooled[f + 2], acc.z);
    atomicAdd(&g_pooled[f + 3], acc.w);
}

// =====================================================================
// 6) tiny GEMM2
// =====================================================================
__global__ __launch_bounds__(512) void k_gemm2(
    const float* __restrict__ W2,
    const float* __restrict__ b2,
    float* __restrict__ out)
{
    __shared__ float p[H_];
    int b = blockIdx.x;
    int j = threadIdx.x;
    float cnt = fmaxf(g_counts[b], 1.f);
    p[j] = g_pooled[b * H_ + j] / cnt;
    __syncthreads();
    float acc = b2[j];
    #pragma unroll 8
    for (int h = 0; h < H_; h++)
        acc = fmaf(p[h], W2[(size_t)h * H_ + j], acc);
    out[b * H_ + j] = acc;
}

// =====================================================================
extern "C" void kernel_launch(void* const* d_in, const int* in_sizes, int n_in,
                              void* d_out, int out_size) {
    const float* hidden = (const float*)d_in[0];
    const int*   mask   = (const int*)  d_in[1];
    const float* W1     = (const float*)d_in[2];
    const float* b1     = (const float*)d_in[3];
    const float* gamma  = (const float*)d_in[4];
    const float* beta   = (const float*)d_in[5];
    const float* W2     = (const float*)d_in[6];
    const float* b2     = (const float*)d_in[7];
    float* out = (float*)d_out;

    cudaFuncSetAttribute(k_gemm_mma,
                         cudaFuncAttributeMaxDynamicSharedMemorySize, SMEM_GEMM);

    k_zero<<<64, 256>>>();
    k_counts<<<B_, 256>>>(mask);
    k_prepW1<<<(H_ * (D_ / 2) + 255) / 256, 256>>>(W1);
    dim3 g1(H_ / 128, M_ / 128);                 // (4, 512)
    k_gemm_mma<<<g1, 256, SMEM_GEMM>>>(hidden, b1, mask);
    k_finalize<<<1, 512>>>(gamma, beta);
    dim3 gp(16, B_);
    k_pool<<<gp, 128>>>(mask);
    k_gemm2<<<B_, 512>>>(W2, b2, out);
}